// round 9
// baseline (speedup 1.0000x reference)
#include <cuda_runtime.h>
#include <cstdint>

// Problem constants.
#define NTOK 16384
#define DIN  2048
#define DOUT 2048
#define NEXP 8

// GEMM tiling: 64x256 CTA tile, 8 warps (32x64 each, 2x4 grid), 2 CTAs/SM.
#define BM 64
#define BN 256
#define BK 32                      // floats per K stage = 128 bytes per row
#define NSTG (DIN / BK)            // 64 stages
#define ST 2                       // cp.async ring depth
#define MAXT (NTOK / BM + NEXP)    // 264 m-tiles worst case
#define PADN (MAXT * BM)           // 16896

// SMEM layout (dynamic, offsets from 1024-aligned base).
#define SM_TOK   0                 // 64 ints
#define SM_STG0  1024
#define STGB     40960             // 40 KB per stage: A(8K) + B(32K)
#define BOFF     8192
#define SMEM_REQ (SM_STG0 + ST * STGB + 1024)   // 84992 (x2 CTAs = 166KB)

#define SW128(o) ((o) ^ (((o) >> 3) & 0x70))

// Scratch (device globals are the sanctioned scratch; no allocations allowed).
__device__ int g_sorted[PADN];
__device__ int g_tile_expert[MAXT];
__device__ __align__(16) float g_Wr[NEXP * DOUT * DIN];   // rna-rounded W
__device__ __align__(16) float g_Xs[PADN * DIN];          // gathered+rounded x

// ---------------------------------------------------------------------------
// PTX helpers (baseline PTX only — no 'a'-suffix features).
// ---------------------------------------------------------------------------
__device__ __forceinline__ void cp16(uint32_t dst, const void* src) {
    asm volatile("cp.async.cg.shared.global [%0], [%1], 16;"
                 :: "r"(dst), "l"(src));
}
__device__ __forceinline__ void cp_commit() {
    asm volatile("cp.async.commit_group;" ::: "memory");
}
__device__ __forceinline__ void cp_wait1() {
    asm volatile("cp.async.wait_group 1;" ::: "memory");
}
__device__ __forceinline__ void ldsm4(uint32_t& r0, uint32_t& r1, uint32_t& r2,
                                      uint32_t& r3, uint32_t addr) {
    asm volatile("ldmatrix.sync.aligned.m8n8.x4.shared.b16 {%0,%1,%2,%3}, [%4];"
                 : "=r"(r0), "=r"(r1), "=r"(r2), "=r"(r3) : "r"(addr));
}
// Round-to-nearest fp32 -> tf32 bits (done once in k_prep, not in GEMM loop).
__device__ __forceinline__ uint32_t rna(uint32_t v) {
    uint32_t r;
    asm("cvt.rna.tf32.f32 %0, %1;" : "=r"(r) : "r"(v));
    return r;
}
__device__ __forceinline__ void mma_tf32(float* d, const uint32_t* a,
                                         const uint32_t* b) {
    asm volatile(
        "mma.sync.aligned.m16n8k8.row.col.f32.tf32.tf32.f32 "
        "{%0,%1,%2,%3}, {%4,%5,%6,%7}, {%8,%9}, {%0,%1,%2,%3};"
        : "+f"(d[0]), "+f"(d[1]), "+f"(d[2]), "+f"(d[3])
        : "r"(a[0]), "r"(a[1]), "r"(a[2]), "r"(a[3]), "r"(b[0]), "r"(b[1]));
}

// ---------------------------------------------------------------------------
// Fused routing: ONE CTA. Pads each expert bucket to a multiple of BM=64.
// ---------------------------------------------------------------------------
__global__ void k_route(const void* __restrict__ idxs) {
    __shared__ int h[NEXP], fill_s[NEXP];
    __shared__ int s_is64;
    const int tid = threadIdx.x;

    if (tid == 0) {
        const int* p = (const int*)idxs;
        int is64 = 1;
        for (int t = 0; t < 32; t++)
            if (p[2 * t + 1] != 0) { is64 = 0; break; }
        s_is64 = is64;
    }
    if (tid < NEXP) h[tid] = 0;
    for (int i = tid; i < PADN; i += 1024) g_sorted[i] = -1;
    __syncthreads();

    const int is64 = s_is64;
    const long long* p64 = (const long long*)idxs;
    const int* p32 = (const int*)idxs;

    for (int i = tid; i < NTOK; i += 1024)
        atomicAdd(&h[is64 ? (int)p64[i] : p32[i]], 1);
    __syncthreads();

    if (tid == 0) {
        int off = 0;
        for (int e = 0; e < NEXP; e++) {
            fill_s[e] = off;
            int nt = (h[e] + BM - 1) / BM;
            for (int t = 0; t < nt; t++) g_tile_expert[off / BM + t] = e;
            off += nt * BM;
        }
        for (int t = off / BM; t < MAXT; t++) g_tile_expert[t] = -1;
    }
    __syncthreads();

    for (int i = tid; i < NTOK; i += 1024) {
        int e = is64 ? (int)p64[i] : p32[i];
        int pos = atomicAdd(&fill_s[e], 1);
        g_sorted[pos] = i;
    }
}

// ---------------------------------------------------------------------------
// Preprocess: round W -> g_Wr; gather + round x into sorted order -> g_Xs
// (padding slots become zero rows, so the GEMM A-path needs no masking).
// ---------------------------------------------------------------------------
__global__ void k_prep(const float* __restrict__ x, const float* __restrict__ W) {
    const int gt = blockIdx.x * blockDim.x + threadIdx.x;
    const int gs = gridDim.x * blockDim.x;

    const uint4* W4 = (const uint4*)W;
    uint4* Wr4 = (uint4*)g_Wr;
    for (int i = gt; i < NEXP * DOUT * DIN / 4; i += gs) {
        uint4 v = W4[i];
        v.x = rna(v.x); v.y = rna(v.y); v.z = rna(v.z); v.w = rna(v.w);
        Wr4[i] = v;
    }

    const uint4* x4 = (const uint4*)x;
    uint4* Xs4 = (uint4*)g_Xs;
    for (int i = gt; i < PADN * DIN / 4; i += gs) {
        const int slot = i >> 9;               // DIN/4 = 512 float4 per row
        const int k4 = i & 511;
        const int tok = g_sorted[slot];
        uint4 v = {0u, 0u, 0u, 0u};
        if (tok >= 0) {
            v = x4[(size_t)tok * 512 + k4];
            v.x = rna(v.x); v.y = rna(v.y); v.z = rna(v.z); v.w = rna(v.w);
        }
        Xs4[i] = v;
    }
}

// ---------------------------------------------------------------------------
// tf32 mma.sync grouped GEMM: 64x256 CTA, 8 warps (32x64 each), BK=32,
// ST=2 double-buffered cp.async, SW128 ldmatrix, cvt-free inner loop,
// 2 CTAs/SM for barrier decoupling.  y[tok] = relu(x[tok] @ W[e]^T + b[e]).
// ---------------------------------------------------------------------------
__global__ void __launch_bounds__(256, 2)
k_gemm_mma(const float* __restrict__ bias, float* __restrict__ out) {
    extern __shared__ char smem_raw[];
    const int mt_blk = blockIdx.y;
    const int e = g_tile_expert[mt_blk];
    if (e < 0) return;
    const int n0 = blockIdx.x * BN;
    const int tid = threadIdx.x;
    const int wid = tid >> 5;
    const int lane = tid & 31;

    uint32_t sraw = (uint32_t)__cvta_generic_to_shared(smem_raw);
    uint32_t sbase = (sraw + 1023) & ~1023u;
    char* smem = smem_raw + (sbase - sraw);
    int* s_tok = (int*)(smem + SM_TOK);

    if (tid < BM) s_tok[tid] = g_sorted[mt_blk * BM + tid];
    __syncthreads();

    // ---- Producer geometry (256 threads):
    // A: 4 threads per row (64 rows), 2x16B chunks.  B: 1 thread/row, 8x16B.
    const int arow = tid >> 2;
    const int acb = (tid & 3) * 2;
    const float* asrc = g_Xs + (size_t)mt_blk * BM * DIN + (size_t)arow * DIN;
    const float* bsrc = g_Wr + (size_t)e * DOUT * DIN + (size_t)(n0 + tid) * DIN;

    uint32_t aoff[2], boff[8];
#pragma unroll
    for (int j = 0; j < 2; j++)
        aoff[j] = SW128((uint32_t)(arow * 128 + (acb + j) * 16));
#pragma unroll
    for (int j = 0; j < 8; j++)
        boff[j] = SW128((uint32_t)(tid * 128 + j * 16));

    auto issue = [&](int it, int bf) {
        const int k0 = it * BK;
        const uint32_t stg = sbase + SM_STG0 + bf * STGB;
#pragma unroll
        for (int j = 0; j < 2; j++)
            cp16(stg + aoff[j], asrc + k0 + (acb + j) * 4);
#pragma unroll
        for (int j = 0; j < 8; j++)
            cp16(stg + BOFF + boff[j], bsrc + k0 + j * 4);
    };

    // ---- ldmatrix lane addressing (32x64 warp tiles, 2x4 warp grid).
    const int g = lane >> 3;
    const int gr = lane & 7;
    const int wm = (wid >> 2) * 32;
    const int wn = (wid & 3) * 64;
    const int a_row_off = wm + ((g & 1) << 3) + gr;
    const int a_kbyte = (g >> 1) << 4;
    const int b_row_off = wn + ((g >> 1) << 3) + gr;
    const int b_kbyte = (g & 1) << 4;

    float acc[2][8][4];
#pragma unroll
    for (int i = 0; i < 2; i++)
#pragma unroll
        for (int j = 0; j < 8; j++)
#pragma unroll
            for (int q = 0; q < 4; q++) acc[i][j][q] = 0.f;

    issue(0, 0); cp_commit();
    issue(1, 1); cp_commit();

    for (int it = 0; it < NSTG; ++it) {
        const int st = it & 1;
        cp_wait1();                          // group 'it' complete
        __syncthreads();

        const uint32_t aS = sbase + SM_STG0 + st * STGB;
        const uint32_t bS = aS + BOFF;
#pragma unroll
        for (int ks = 0; ks < 4; ks++) {
            uint32_t aF[2][4], bF[8][2];
#pragma unroll
            for (int mt = 0; mt < 2; mt++) {
                uint32_t addr = aS + SW128((uint32_t)((a_row_off + mt * 16) * 128
                                                      + ks * 32 + a_kbyte));
                ldsm4(aF[mt][0], aF[mt][1], aF[mt][2], aF[mt][3], addr);
            }
#pragma unroll
            for (int ntp = 0; ntp < 4; ntp++) {
                uint32_t addr = bS + SW128((uint32_t)((b_row_off + ntp * 16) * 128
                                                      + ks * 32 + b_kbyte));
                ldsm4(bF[2 * ntp][0], bF[2 * ntp][1],
                      bF[2 * ntp + 1][0], bF[2 * ntp + 1][1], addr);
            }
#pragma unroll
            for (int mt = 0; mt < 2; mt++)
#pragma unroll
                for (int nt = 0; nt < 8; nt++)
                    mma_tf32(acc[mt][nt], aF[mt], bF[nt]);
        }

        __syncthreads();                     // all warps done with stage st
        if (it + 2 < NSTG) issue(it + 2, st);
        cp_commit();                         // empty commits at tail keep count
    }

    // ---- Epilogue: bias + ReLU, scatter to token rows.
    const int erow = wm + (lane >> 2);
    const int ecol = n0 + wn + ((lane & 3) << 1);
    float2 bv[8];
#pragma unroll
    for (int nt = 0; nt < 8; nt++)
        bv[nt] = *(const float2*)&bias[(size_t)e * DOUT + ecol + nt * 8];

#pragma unroll
    for (int mt = 0; mt < 2; mt++) {
#pragma unroll
        for (int v = 0; v < 2; v++) {
            const int row = erow + mt * 16 + v * 8;
            const int tok = s_tok[row];
            if (tok < 0) continue;
            float* o = out + (size_t)tok * DOUT + ecol;
#pragma unroll
            for (int nt = 0; nt < 8; nt++) {
                float2 r;
                r.x = fmaxf(acc[mt][nt][2 * v + 0] + bv[nt].x, 0.f);
                r.y = fmaxf(acc[mt][nt][2 * v + 1] + bv[nt].y, 0.f);
                *(float2*)(o + nt * 8) = r;
            }
        }
    }
}

// ---------------------------------------------------------------------------
// Launch: 3 kernels per call (route, prep, gemm).
// ---------------------------------------------------------------------------
extern "C" void kernel_launch(void* const* d_in, const int* in_sizes, int n_in,
                              void* d_out, int out_size) {
    const float* x    = (const float*)d_in[0];
    const void*  idxs = d_in[1];
    const float* W    = (const float*)d_in[2];
    const float* b    = (const float*)d_in[3];
    float* out = (float*)d_out;

    k_route<<<1, 1024>>>(idxs);
    k_prep<<<2048, 256>>>(x, W);

    cudaFuncSetAttribute(k_gemm_mma, cudaFuncAttributeMaxDynamicSharedMemorySize,
                         SMEM_REQ);
    dim3 grid(DOUT / BN, MAXT);            // (8, 264)
    k_gemm_mma<<<grid, 256, SMEM_REQ>>>(b, out);
}

// round 10
// speedup vs baseline: 1.9693x; 1.9693x over previous
#include <cuda_runtime.h>
#include <cstdint>

// Problem constants.
#define NTOK 16384
#define DIN  2048
#define DOUT 2048
#define NEXP 8

// GEMM tiling: 128x256 CTA tile, 16 warps (32x64 each, 4x4 grid), BK=64.
#define BM 128
#define BN 256
#define BK 64                      // floats per K stage = 256B per row (2 panels)
#define NSTG (DIN / BK)            // 32 stages
#define ST 2                       // cp.async ring depth
#define MAXT (NTOK / BM + NEXP)    // 136 m-tiles worst case
#define PADN (MAXT * BM)           // 17408

// SMEM layout (dynamic, offsets from 1024-aligned base).
// Stage = [A pan0 16K][A pan1 16K][B pan0 32K][B pan1 32K] = 96 KB.
#define SM_TOK   0                 // 128 ints
#define SM_STG0  1024
#define STGB     98304
#define APAN     16384
#define BBASE    32768
#define BPAN     32768
#define SMEM_REQ (SM_STG0 + ST * STGB + 1024)   // 198656 (<= 227KB opt-in)

#define SW128(o) ((o) ^ (((o) >> 3) & 0x70))

// Scratch (device globals are the sanctioned scratch; no allocations allowed).
__device__ int g_sorted[PADN];
__device__ int g_tile_expert[MAXT];
__device__ __align__(16) float g_Wr[NEXP * DOUT * DIN];   // rna-rounded W
__device__ __align__(16) float g_Xs[PADN * DIN];          // gathered+rounded x

// ---------------------------------------------------------------------------
// PTX helpers (baseline PTX only — no 'a'-suffix features).
// ---------------------------------------------------------------------------
__device__ __forceinline__ void cp16(uint32_t dst, const void* src) {
    asm volatile("cp.async.cg.shared.global [%0], [%1], 16;"
                 :: "r"(dst), "l"(src));
}
__device__ __forceinline__ void cp_commit() {
    asm volatile("cp.async.commit_group;" ::: "memory");
}
__device__ __forceinline__ void cp_wait0() {
    asm volatile("cp.async.wait_group 0;" ::: "memory");
}
__device__ __forceinline__ void ldsm4(uint32_t& r0, uint32_t& r1, uint32_t& r2,
                                      uint32_t& r3, uint32_t addr) {
    asm volatile("ldmatrix.sync.aligned.m8n8.x4.shared.b16 {%0,%1,%2,%3}, [%4];"
                 : "=r"(r0), "=r"(r1), "=r"(r2), "=r"(r3) : "r"(addr));
}
// Round-to-nearest fp32 -> tf32 bits (done once in k_prep, not in GEMM loop).
__device__ __forceinline__ uint32_t rna(uint32_t v) {
    uint32_t r;
    asm("cvt.rna.tf32.f32 %0, %1;" : "=r"(r) : "r"(v));
    return r;
}
__device__ __forceinline__ void mma_tf32(float* d, const uint32_t* a,
                                         const uint32_t* b) {
    asm volatile(
        "mma.sync.aligned.m16n8k8.row.col.f32.tf32.tf32.f32 "
        "{%0,%1,%2,%3}, {%4,%5,%6,%7}, {%8,%9}, {%0,%1,%2,%3};"
        : "+f"(d[0]), "+f"(d[1]), "+f"(d[2]), "+f"(d[3])
        : "r"(a[0]), "r"(a[1]), "r"(a[2]), "r"(a[3]), "r"(b[0]), "r"(b[1]));
}

// ---------------------------------------------------------------------------
// Fused routing: ONE CTA.
// ---------------------------------------------------------------------------
__global__ void k_route(const void* __restrict__ idxs) {
    __shared__ int h[NEXP], fill_s[NEXP];
    __shared__ int s_is64;
    const int tid = threadIdx.x;

    if (tid == 0) {
        const int* p = (const int*)idxs;
        int is64 = 1;
        for (int t = 0; t < 32; t++)
            if (p[2 * t + 1] != 0) { is64 = 0; break; }
        s_is64 = is64;
    }
    if (tid < NEXP) h[tid] = 0;
    for (int i = tid; i < PADN; i += 1024) g_sorted[i] = -1;
    __syncthreads();

    const int is64 = s_is64;
    const long long* p64 = (const long long*)idxs;
    const int* p32 = (const int*)idxs;

    for (int i = tid; i < NTOK; i += 1024)
        atomicAdd(&h[is64 ? (int)p64[i] : p32[i]], 1);
    __syncthreads();

    if (tid == 0) {
        int off = 0;
        for (int e = 0; e < NEXP; e++) {
            fill_s[e] = off;
            int nt = (h[e] + BM - 1) / BM;
            for (int t = 0; t < nt; t++) g_tile_expert[off / BM + t] = e;
            off += nt * BM;
        }
        for (int t = off / BM; t < MAXT; t++) g_tile_expert[t] = -1;
    }
    __syncthreads();

    for (int i = tid; i < NTOK; i += 1024) {
        int e = is64 ? (int)p64[i] : p32[i];
        int pos = atomicAdd(&fill_s[e], 1);
        g_sorted[pos] = i;
    }
}

// ---------------------------------------------------------------------------
// Preprocess: round W -> g_Wr; gather + round x into sorted order -> g_Xs.
// ---------------------------------------------------------------------------
__global__ void k_prep(const float* __restrict__ x, const float* __restrict__ W) {
    const int gt = blockIdx.x * blockDim.x + threadIdx.x;
    const int gs = gridDim.x * blockDim.x;

    const uint4* W4 = (const uint4*)W;
    uint4* Wr4 = (uint4*)g_Wr;
    for (int i = gt; i < NEXP * DOUT * DIN / 4; i += gs) {
        uint4 v = W4[i];
        v.x = rna(v.x); v.y = rna(v.y); v.z = rna(v.z); v.w = rna(v.w);
        Wr4[i] = v;
    }

    const uint4* x4 = (const uint4*)x;
    uint4* Xs4 = (uint4*)g_Xs;
    for (int i = gt; i < PADN * DIN / 4; i += gs) {
        const int slot = i >> 9;               // DIN/4 = 512 float4 per row
        const int k4 = i & 511;
        const int tok = g_sorted[slot];
        uint4 v = {0u, 0u, 0u, 0u};
        if (tok >= 0) {
            v = x4[(size_t)tok * 512 + k4];
            v.x = rna(v.x); v.y = rna(v.y); v.z = rna(v.z); v.w = rna(v.w);
        }
        Xs4[i] = v;
    }
}

// ---------------------------------------------------------------------------
// tf32 mma.sync grouped GEMM: 128x256 CTA, 16 warps (32x64 each), BK=64
// (2x128B panels), ST=2 ring, one sync per 64-K stage, SW128 ldmatrix,
// cvt-free inner loop.  y[tok] = relu(x[tok] @ W[e]^T + b[e]).
// ---------------------------------------------------------------------------
__global__ void __launch_bounds__(512, 1)
k_gemm_mma(const float* __restrict__ bias, float* __restrict__ out) {
    extern __shared__ char smem_raw[];
    const int mt_blk = blockIdx.y;
    const int e = g_tile_expert[mt_blk];
    if (e < 0) return;
    const int n0 = blockIdx.x * BN;
    const int tid = threadIdx.x;
    const int wid = tid >> 5;
    const int lane = tid & 31;

    uint32_t sraw = (uint32_t)__cvta_generic_to_shared(smem_raw);
    uint32_t sbase = (sraw + 1023) & ~1023u;
    char* smem = smem_raw + (sbase - sraw);
    int* s_tok = (int*)(smem + SM_TOK);

    if (tid < BM) s_tok[tid] = g_sorted[mt_blk * BM + tid];
    __syncthreads();

    // ---- Producer geometry (512 threads, 96 KB/stage):
    // A: 4 threads/row (128 rows x 256B), 4x16B chunks each.
    // B: 2 threads/row (256 rows x 256B), one 128B panel (8x16B) each.
    const int arow = tid >> 2;
    const int acb = (tid & 3) * 4;             // chunk base in 16B units (0..15)
    const float* asrc = g_Xs + (size_t)mt_blk * BM * DIN + (size_t)arow * DIN;
    const int brow = tid >> 1;
    const int bpan = tid & 1;
    const float* bsrc = g_Wr + (size_t)e * DOUT * DIN + (size_t)(n0 + brow) * DIN;

    uint32_t aoff[4], boff[8];
#pragma unroll
    for (int j = 0; j < 4; j++) {
        const int u = acb + j;                 // 16B unit within 256B row
        aoff[j] = (u >> 3) * APAN + SW128((uint32_t)(arow * 128 + (u & 7) * 16));
    }
#pragma unroll
    for (int j = 0; j < 8; j++)
        boff[j] = BBASE + bpan * BPAN + SW128((uint32_t)(brow * 128 + j * 16));

    auto issue = [&](int it, int bf) {
        const int k0 = it * BK;
        const uint32_t stg = sbase + SM_STG0 + bf * STGB;
#pragma unroll
        for (int j = 0; j < 4; j++)
            cp16(stg + aoff[j], asrc + k0 + (acb + j) * 4);
#pragma unroll
        for (int j = 0; j < 8; j++)
            cp16(stg + boff[j], bsrc + k0 + bpan * 32 + j * 4);
    };

    // ---- ldmatrix lane addressing (32x64 warp tiles, 4x4 warp grid).
    const int g = lane >> 3;
    const int gr = lane & 7;
    const int wm = (wid >> 2) * 32;
    const int wn = (wid & 3) * 64;
    const int a_row_off = wm + ((g & 1) << 3) + gr;
    const int a_kbyte = (g >> 1) << 4;
    const int b_row_off = wn + ((g >> 1) << 3) + gr;
    const int b_kbyte = (g & 1) << 4;

    float acc[2][8][4];
#pragma unroll
    for (int i = 0; i < 2; i++)
#pragma unroll
        for (int j = 0; j < 8; j++)
#pragma unroll
            for (int q = 0; q < 4; q++) acc[i][j][q] = 0.f;

    issue(0, 0); cp_commit();

    for (int it = 0; it < NSTG; ++it) {
        const int st = it & 1;
        cp_wait0();                          // stage 'it' resident
        __syncthreads();                     // also: everyone done with buf st^1
        if (it + 1 < NSTG) { issue(it + 1, st ^ 1); cp_commit(); }

        const uint32_t aS = sbase + SM_STG0 + st * STGB;
        const uint32_t bS = aS + BBASE;
#pragma unroll
        for (int ks = 0; ks < 8; ks++) {
            const int pan = ks >> 2;
            const int ksl = ks & 3;
            uint32_t aF[2][4], bF[8][2];
#pragma unroll
            for (int mt = 0; mt < 2; mt++) {
                uint32_t addr = aS + pan * APAN
                    + SW128((uint32_t)((a_row_off + mt * 16) * 128
                                       + ksl * 32 + a_kbyte));
                ldsm4(aF[mt][0], aF[mt][1], aF[mt][2], aF[mt][3], addr);
            }
#pragma unroll
            for (int ntp = 0; ntp < 4; ntp++) {
                uint32_t addr = bS + pan * BPAN
                    + SW128((uint32_t)((b_row_off + ntp * 16) * 128
                                       + ksl * 32 + b_kbyte));
                ldsm4(bF[2 * ntp][0], bF[2 * ntp][1],
                      bF[2 * ntp + 1][0], bF[2 * ntp + 1][1], addr);
            }
#pragma unroll
            for (int mt = 0; mt < 2; mt++)
#pragma unroll
                for (int nt = 0; nt < 8; nt++)
                    mma_tf32(acc[mt][nt], aF[mt], bF[nt]);
        }
    }

    // ---- Epilogue: bias + ReLU, scatter to token rows.
    const int erow = wm + (lane >> 2);
    const int ecol = n0 + wn + ((lane & 3) << 1);
    float2 bv[8];
#pragma unroll
    for (int nt = 0; nt < 8; nt++)
        bv[nt] = *(const float2*)&bias[(size_t)e * DOUT + ecol + nt * 8];

#pragma unroll
    for (int mt = 0; mt < 2; mt++) {
#pragma unroll
        for (int v = 0; v < 2; v++) {
            const int row = erow + mt * 16 + v * 8;
            const int tok = s_tok[row];
            if (tok < 0) continue;
            float* o = out + (size_t)tok * DOUT + ecol;
#pragma unroll
            for (int nt = 0; nt < 8; nt++) {
                float2 r;
                r.x = fmaxf(acc[mt][nt][2 * v + 0] + bv[nt].x, 0.f);
                r.y = fmaxf(acc[mt][nt][2 * v + 1] + bv[nt].y, 0.f);
                *(float2*)(o + nt * 8) = r;
            }
        }
    }
}

// ---------------------------------------------------------------------------
// Launch: 3 kernels per call (route, prep, gemm).
// ---------------------------------------------------------------------------
extern "C" void kernel_launch(void* const* d_in, const int* in_sizes, int n_in,
                              void* d_out, int out_size) {
    const float* x    = (const float*)d_in[0];
    const void*  idxs = d_in[1];
    const float* W    = (const float*)d_in[2];
    const float* b    = (const float*)d_in[3];
    float* out = (float*)d_out;

    k_route<<<1, 1024>>>(idxs);
    k_prep<<<2048, 256>>>(x, W);

    cudaFuncSetAttribute(k_gemm_mma, cudaFuncAttributeMaxDynamicSharedMemorySize,
                         SMEM_REQ);
    dim3 grid(DOUT / BN, MAXT);            // (8, 136)
    k_gemm_mma<<<grid, 512, SMEM_REQ>>>(b, out);
}

// round 11
// speedup vs baseline: 2.5306x; 1.2850x over previous
#include <cuda_runtime.h>
#include <cstdint>

// Problem constants.
#define NTOK 16384
#define DIN  2048
#define DOUT 2048
#define NEXP 8

// GEMM tiling: 128x256 CTA tile, 16 warps (32x64 each, 4x4 grid).
#define BM 128
#define BN 256
#define BK 32                      // floats per K stage = 128 bytes per row
#define NSTG (DIN / BK)            // 64 stages
#define ST 4                       // cp.async ring depth
#define MAXT (NTOK / BM + NEXP)    // 136 m-tiles worst case
#define PADN (MAXT * BM)           // 17408

// SMEM layout (dynamic, offsets from 1024-aligned base).
#define SM_TOK   0                 // 128 ints
#define SM_STG0  1024
#define STGB     49152             // 48 KB per stage: A(16K) + B(32K)
#define BOFF     16384
#define SMEM_REQ (SM_STG0 + ST * STGB + 1024)

#define SW128(o) ((o) ^ (((o) >> 3) & 0x70))

// Scratch (device globals are the sanctioned scratch; no allocations allowed).
__device__ int g_sorted[PADN];
__device__ int g_tile_expert[MAXT];
__device__ __align__(16) float g_Wr[NEXP * DOUT * DIN];   // rna-rounded W
__device__ __align__(16) float g_Xs[PADN * DIN];          // gathered+rounded x

// ---------------------------------------------------------------------------
// PTX helpers (baseline PTX only — no 'a'-suffix features).
// ---------------------------------------------------------------------------
__device__ __forceinline__ void cp16(uint32_t dst, const void* src) {
    asm volatile("cp.async.cg.shared.global [%0], [%1], 16;"
                 :: "r"(dst), "l"(src));
}
__device__ __forceinline__ void cp_commit() {
    asm volatile("cp.async.commit_group;" ::: "memory");
}
__device__ __forceinline__ void cp_wait2() {
    asm volatile("cp.async.wait_group 2;" ::: "memory");
}
__device__ __forceinline__ void ldsm4(uint32_t& r0, uint32_t& r1, uint32_t& r2,
                                      uint32_t& r3, uint32_t addr) {
    asm volatile("ldmatrix.sync.aligned.m8n8.x4.shared.b16 {%0,%1,%2,%3}, [%4];"
                 : "=r"(r0), "=r"(r1), "=r"(r2), "=r"(r3) : "r"(addr));
}
// Round-to-nearest fp32 -> tf32 bits (done once in k_prep, not in GEMM loop).
__device__ __forceinline__ uint32_t rna(uint32_t v) {
    uint32_t r;
    asm("cvt.rna.tf32.f32 %0, %1;" : "=r"(r) : "r"(v));
    return r;
}
__device__ __forceinline__ void mma_tf32(float* d, const uint32_t* a,
                                         const uint32_t* b) {
    asm volatile(
        "mma.sync.aligned.m16n8k8.row.col.f32.tf32.tf32.f32 "
        "{%0,%1,%2,%3}, {%4,%5,%6,%7}, {%8,%9}, {%0,%1,%2,%3};"
        : "+f"(d[0]), "+f"(d[1]), "+f"(d[2]), "+f"(d[3])
        : "r"(a[0]), "r"(a[1]), "r"(a[2]), "r"(a[3]), "r"(b[0]), "r"(b[1]));
}

// ---------------------------------------------------------------------------
// Fused routing: ONE CTA.
// ---------------------------------------------------------------------------
__global__ void k_route(const void* __restrict__ idxs) {
    __shared__ int h[NEXP], fill_s[NEXP];
    __shared__ int s_is64;
    const int tid = threadIdx.x;

    if (tid == 0) {
        const int* p = (const int*)idxs;
        int is64 = 1;
        for (int t = 0; t < 32; t++)
            if (p[2 * t + 1] != 0) { is64 = 0; break; }
        s_is64 = is64;
    }
    if (tid < NEXP) h[tid] = 0;
    for (int i = tid; i < PADN; i += 1024) g_sorted[i] = -1;
    __syncthreads();

    const int is64 = s_is64;
    const long long* p64 = (const long long*)idxs;
    const int* p32 = (const int*)idxs;

    for (int i = tid; i < NTOK; i += 1024)
        atomicAdd(&h[is64 ? (int)p64[i] : p32[i]], 1);
    __syncthreads();

    if (tid == 0) {
        int off = 0;
        for (int e = 0; e < NEXP; e++) {
            fill_s[e] = off;
            int nt = (h[e] + BM - 1) / BM;
            for (int t = 0; t < nt; t++) g_tile_expert[off / BM + t] = e;
            off += nt * BM;
        }
        for (int t = off / BM; t < MAXT; t++) g_tile_expert[t] = -1;
    }
    __syncthreads();

    for (int i = tid; i < NTOK; i += 1024) {
        int e = is64 ? (int)p64[i] : p32[i];
        int pos = atomicAdd(&fill_s[e], 1);
        g_sorted[pos] = i;
    }
}

// ---------------------------------------------------------------------------
// Preprocess: round W -> g_Wr; gather + round x into sorted order -> g_Xs.
// ---------------------------------------------------------------------------
__global__ void k_prep(const float* __restrict__ x, const float* __restrict__ W) {
    const int gt = blockIdx.x * blockDim.x + threadIdx.x;
    const int gs = gridDim.x * blockDim.x;

    const uint4* W4 = (const uint4*)W;
    uint4* Wr4 = (uint4*)g_Wr;
    for (int i = gt; i < NEXP * DOUT * DIN / 4; i += gs) {
        uint4 v = W4[i];
        v.x = rna(v.x); v.y = rna(v.y); v.z = rna(v.z); v.w = rna(v.w);
        Wr4[i] = v;
    }

    const uint4* x4 = (const uint4*)x;
    uint4* Xs4 = (uint4*)g_Xs;
    for (int i = gt; i < PADN * DIN / 4; i += gs) {
        const int slot = i >> 9;               // DIN/4 = 512 float4 per row
        const int k4 = i & 511;
        const int tok = g_sorted[slot];
        uint4 v = {0u, 0u, 0u, 0u};
        if (tok >= 0) {
            v = x4[(size_t)tok * 512 + k4];
            v.x = rna(v.x); v.y = rna(v.y); v.z = rna(v.z); v.w = rna(v.w);
        }
        Xs4[i] = v;
    }
}

// ---------------------------------------------------------------------------
// tf32 mma.sync grouped GEMM: 128x256 CTA, 16 warps (32x64 each), BK=32,
// ST=4 cp.async ring (prefetch distance 2), one sync per stage, SW128
// ldmatrix, cvt-free inner loop, per-warp ks rotation to de-phase the
// crossbar/tensor bursts.  y[tok] = relu(x[tok] @ W[e]^T + b[e]).
// ---------------------------------------------------------------------------
__global__ void __launch_bounds__(512, 1)
k_gemm_mma(const float* __restrict__ bias, float* __restrict__ out) {
    extern __shared__ char smem_raw[];
    const int mt_blk = blockIdx.y;
    const int e = g_tile_expert[mt_blk];
    if (e < 0) return;
    const int n0 = blockIdx.x * BN;
    const int tid = threadIdx.x;
    const int wid = tid >> 5;
    const int lane = tid & 31;

    uint32_t sraw = (uint32_t)__cvta_generic_to_shared(smem_raw);
    uint32_t sbase = (sraw + 1023) & ~1023u;
    char* smem = smem_raw + (sbase - sraw);
    int* s_tok = (int*)(smem + SM_TOK);

    if (tid < BM) s_tok[tid] = g_sorted[mt_blk * BM + tid];
    __syncthreads();

    // ---- Producer geometry (512 threads):
    // A: 4 threads per row, 2x16B chunks each.  B: 2 threads per row, 4x16B.
    const int arow = tid >> 2;
    const int acb = (tid & 3) * 2;
    const float* asrc = g_Xs + (size_t)mt_blk * BM * DIN + (size_t)arow * DIN;
    const int brow = tid >> 1;
    const int bcb = (tid & 1) * 4;
    const float* bsrc = g_Wr + (size_t)e * DOUT * DIN + (size_t)(n0 + brow) * DIN;

    uint32_t aoff[2], boff[4];
#pragma unroll
    for (int j = 0; j < 2; j++)
        aoff[j] = SW128((uint32_t)(arow * 128 + (acb + j) * 16));
#pragma unroll
    for (int j = 0; j < 4; j++)
        boff[j] = SW128((uint32_t)(brow * 128 + (bcb + j) * 16));

    auto issue = [&](int it, int bf) {
        const int k0 = it * BK;
        const uint32_t stg = sbase + SM_STG0 + bf * STGB;
#pragma unroll
        for (int j = 0; j < 2; j++)
            cp16(stg + aoff[j], asrc + k0 + (acb + j) * 4);
#pragma unroll
        for (int j = 0; j < 4; j++)
            cp16(stg + BOFF + boff[j], bsrc + k0 + (bcb + j) * 4);
    };

    // ---- ldmatrix lane addressing (32x64 warp tiles, 4x4 warp grid).
    const int g = lane >> 3;
    const int gr = lane & 7;
    const int wm = (wid >> 2) * 32;
    const int wn = (wid & 3) * 64;
    const int a_row_off = wm + ((g & 1) << 3) + gr;
    const int a_kbyte = (g >> 1) << 4;
    const int b_row_off = wn + ((g >> 1) << 3) + gr;
    const int b_kbyte = (g & 1) << 4;
    const int kphase = wid & 3;                // per-warp ks rotation

    float acc[2][8][4];
#pragma unroll
    for (int i = 0; i < 2; i++)
#pragma unroll
        for (int j = 0; j < 8; j++)
#pragma unroll
            for (int q = 0; q < 4; q++) acc[i][j][q] = 0.f;

    issue(0, 0); cp_commit();
    issue(1, 1); cp_commit();
    issue(2, 2); cp_commit();

    for (int it = 0; it < NSTG; ++it) {
        const int st = it & (ST - 1);
        cp_wait2();                          // group 'it' complete, 2 in flight
        __syncthreads();
        if (it + 3 < NSTG) issue(it + 3, (it + 3) & (ST - 1));
        cp_commit();                         // empty commits at tail keep count

        const uint32_t aS = sbase + SM_STG0 + st * STGB;
        const uint32_t bS = aS + BOFF;
#pragma unroll
        for (int ks = 0; ks < 4; ks++) {
            const int ke = (ks + kphase) & 3;   // de-phase warps within stage
            uint32_t aF[2][4], bF[8][2];
#pragma unroll
            for (int mt = 0; mt < 2; mt++) {
                uint32_t addr = aS + SW128((uint32_t)((a_row_off + mt * 16) * 128
                                                      + ke * 32 + a_kbyte));
                ldsm4(aF[mt][0], aF[mt][1], aF[mt][2], aF[mt][3], addr);
            }
#pragma unroll
            for (int ntp = 0; ntp < 4; ntp++) {
                uint32_t addr = bS + SW128((uint32_t)((b_row_off + ntp * 16) * 128
                                                      + ke * 32 + b_kbyte));
                ldsm4(bF[2 * ntp][0], bF[2 * ntp][1],
                      bF[2 * ntp + 1][0], bF[2 * ntp + 1][1], addr);
            }
#pragma unroll
            for (int mt = 0; mt < 2; mt++)
#pragma unroll
                for (int nt = 0; nt < 8; nt++)
                    mma_tf32(acc[mt][nt], aF[mt], bF[nt]);
        }
    }

    // ---- Epilogue: bias + ReLU, scatter to token rows.
    const int erow = wm + (lane >> 2);
    const int ecol = n0 + wn + ((lane & 3) << 1);
    float2 bv[8];
#pragma unroll
    for (int nt = 0; nt < 8; nt++)
        bv[nt] = *(const float2*)&bias[(size_t)e * DOUT + ecol + nt * 8];

#pragma unroll
    for (int mt = 0; mt < 2; mt++) {
#pragma unroll
        for (int v = 0; v < 2; v++) {
            const int row = erow + mt * 16 + v * 8;
            const int tok = s_tok[row];
            if (tok < 0) continue;
            float* o = out + (size_t)tok * DOUT + ecol;
#pragma unroll
            for (int nt = 0; nt < 8; nt++) {
                float2 r;
                r.x = fmaxf(acc[mt][nt][2 * v + 0] + bv[nt].x, 0.f);
                r.y = fmaxf(acc[mt][nt][2 * v + 1] + bv[nt].y, 0.f);
                *(float2*)(o + nt * 8) = r;
            }
        }
    }
}

// ---------------------------------------------------------------------------
// Launch: 3 kernels per call (route, prep, gemm).
// ---------------------------------------------------------------------------
extern "C" void kernel_launch(void* const* d_in, const int* in_sizes, int n_in,
                              void* d_out, int out_size) {
    const float* x    = (const float*)d_in[0];
    const void*  idxs = d_in[1];
    const float* W    = (const float*)d_in[2];
    const float* b    = (const float*)d_in[3];
    float* out = (float*)d_out;

    k_route<<<1, 1024>>>(idxs);
    k_prep<<<2048, 256>>>(x, W);

    cudaFuncSetAttribute(k_gemm_mma, cudaFuncAttributeMaxDynamicSharedMemorySize,
                         SMEM_REQ);
    dim3 grid(DOUT / BN, MAXT);            // (8, 136)
    k_gemm_mma<<<grid, 512, SMEM_REQ>>>(b, out);
}